// round 8
// baseline (speedup 1.0000x reference)
#include <cuda_runtime.h>
#include <cstdint>

#define DDEPTH 8
#define HDIM   4096
#define HALF   (HDIM / 2)   // 2048 per CTA
#define NT     512
#define NWARP  (NT / 32)    // 16
#define HPT    4            // hidden dims per thread (512*4 = 2048)
#define EPSV   1e-6f

__device__ __forceinline__ uint32_t smem_u32(const void* p) {
    uint32_t a;
    asm("{ .reg .u64 t; cvta.to.shared.u64 t, %1; cvt.u32.u64 %0, t; }"
        : "=r"(a) : "l"(p));
    return a;
}

// 2-CTA cluster per (s,b) site; each CTA owns half of H, ONE float4 per depth
// per thread (32 value regs). All depths loaded in a single burst; single
// reduction; 16-float DSMEM exchange with per-thread cluster-scope release
// arrives (count=16 barrier). 64-reg cap -> 2 CTAs/SM -> 32 warps/SM.
__global__ __launch_bounds__(NT, 2) __cluster_dims__(2, 1, 1)
void fullattnres_kernel(const float* __restrict__ values,
                        const float* __restrict__ query,
                        const float* __restrict__ weight,
                        float* __restrict__ out,
                        int SB)
{
    __shared__ float red[NWARP][16];   // per-warp partials
    __shared__ float fin[16];          // this CTA's half-sums [0..7]=ss [8..15]=dp
    __shared__ float mbox[16];         // peer CTA's half-sums (written remotely)
    __shared__ unsigned long long mbar;

    const int tid  = threadIdx.x;
    const int lane = tid & 31;
    const int warp = tid >> 5;
    const unsigned rank = blockIdx.x & 1;      // cluster rank (cluster_dims x=2)
    const unsigned peer = rank ^ 1u;
    const int site = blockIdx.x >> 1;
    const int h    = (int)rank * HALF + tid * HPT;

    const uint32_t mb_a   = smem_u32(&mbar);
    const uint32_t mbox_a = smem_u32(mbox);

    // init mbarrier: 16 arrivals expected (one per peer reducer thread)
    if (tid == 0)
        asm volatile("mbarrier.init.shared.b64 [%0], %1;" :: "r"(mb_a), "r"(16) : "memory");
    __syncthreads();
    // non-blocking cluster arrive; matching wait deferred until the exchange,
    // so the load burst overlaps cluster startup skew.
    asm volatile("barrier.cluster.arrive.aligned;" ::: "memory");

    // ── Load ALL depths up front: 8 independent LDG.128 per thread ──
    const size_t base = (size_t)site * HDIM + h;
    const size_t dstr = (size_t)SB * HDIM;
    const float* p    = values + base;

    float4 va[DDEPTH];
    #pragma unroll
    for (int d = 0; d < DDEPTH; d++)
        va[d] = *(const float4*)(p + (size_t)d * dstr);

    // fused q*w for this thread's 4 dims (L2-resident)
    const float4 q0 = *(const float4*)(query + h);
    const float4 w0 = *(const float4*)(weight + h);
    const float4 qw = make_float4(q0.x*w0.x, q0.y*w0.y, q0.z*w0.z, q0.w*w0.w);

    // per-thread partials for all depths
    float ss[DDEPTH], dp[DDEPTH];
    #pragma unroll
    for (int d = 0; d < DDEPTH; d++) {
        ss[d] = va[d].x*va[d].x + va[d].y*va[d].y + va[d].z*va[d].z + va[d].w*va[d].w;
        dp[d] = qw.x*va[d].x + qw.y*va[d].y + qw.z*va[d].z + qw.w*va[d].w;
    }

    // ── single warp butterfly over 16 scalars ──
    #pragma unroll
    for (int off = 16; off > 0; off >>= 1) {
        #pragma unroll
        for (int d = 0; d < DDEPTH; d++) {
            ss[d] += __shfl_xor_sync(0xFFFFFFFFu, ss[d], off);
            dp[d] += __shfl_xor_sync(0xFFFFFFFFu, dp[d], off);
        }
    }
    if (lane == 0) {
        #pragma unroll
        for (int d = 0; d < DDEPTH; d++) {
            red[warp][d]     = ss[d];
            red[warp][8 + d] = dp[d];
        }
    }
    __syncthreads();

    // cross-warp: 16 threads each own one scalar (16 adds)
    if (tid < 16) {
        float s = 0.f;
        #pragma unroll
        for (int w2 = 0; w2 < NWARP; w2++) s += red[w2][tid];
        fin[tid] = s;
    }
    __syncthreads();

    // ── DSMEM exchange of the 16 half-sums with the peer CTA ──
    asm volatile("barrier.cluster.wait.aligned;" ::: "memory");  // peer mbar ready
    if (tid < 16) {
        const float v = fin[tid];
        uint32_t ra_box, ra_bar;
        asm volatile("mapa.shared::cluster.u32 %0, %1, %2;"
                     : "=r"(ra_box) : "r"(mbox_a + tid * 4), "r"(peer));
        asm volatile("st.shared::cluster.f32 [%0], %1;"
                     :: "r"(ra_box), "f"(v) : "memory");
        asm volatile("mapa.shared::cluster.u32 %0, %1, %2;"
                     : "=r"(ra_bar) : "r"(mb_a), "r"(peer));
        // cluster-scope RELEASE arrive pairs with the peer's acquire wait.
        asm volatile("mbarrier.arrive.release.cluster.shared::cluster.b64 _, [%0];"
                     :: "r"(ra_bar) : "memory");
    }
    // wait for all 16 peer scalars (parity 0, cluster-scope acquire)
    {
        uint32_t done;
        asm volatile(
            "{ .reg .pred p;"
            "  mbarrier.try_wait.parity.acquire.cluster.shared::cta.b64 p, [%1], %2;"
            "  selp.b32 %0, 1, 0, p; }"
            : "=r"(done) : "r"(mb_a), "r"(0u) : "memory");
        if (!done) {
            asm volatile(
                "{ .reg .pred P1;"
                "WAIT_LOOP_%=:"
                "  mbarrier.try_wait.parity.acquire.cluster.shared::cta.b64 P1, [%0], %1, 0x989680;"
                "  @P1 bra.uni WAIT_DONE_%=;"
                "  bra.uni WAIT_LOOP_%=;"
                "WAIT_DONE_%=: }"
                :: "r"(mb_a), "r"(0u) : "memory");
        }
    }

    // ── softmax over depth (redundant per thread; broadcast LDS) ──
    float wt[DDEPTH];
    float mx = -3.402823466e38f;
    #pragma unroll
    for (int d = 0; d < DDEPTH; d++) {
        const float sst   = fin[d]     + mbox[d];
        const float dpt   = fin[8 + d] + mbox[8 + d];
        const float logit = dpt * rsqrtf(sst * (1.0f / HDIM) + EPSV);
        wt[d] = logit;
        mx = fmaxf(mx, logit);
    }
    float sum = 0.f;
    #pragma unroll
    for (int d = 0; d < DDEPTH; d++) {
        wt[d] = __expf(wt[d] - mx);
        sum += wt[d];
    }
    const float inv = 1.0f / sum;

    // ── combine straight from registers; one float4 store ──
    float4 o = make_float4(0.f, 0.f, 0.f, 0.f);
    #pragma unroll
    for (int d = 0; d < DDEPTH; d++) {
        const float wd = wt[d] * inv;
        o.x += wd * va[d].x;
        o.y += wd * va[d].y;
        o.z += wd * va[d].z;
        o.w += wd * va[d].w;
    }
    *(float4*)(out + base) = o;
    // No trailing cluster sync: passing the acquire-wait proves all remote
    // traffic to this CTA landed, and the peer can't pass its wait until our
    // release-arrives (issued after our remote stores) are visible.
}

extern "C" void kernel_launch(void* const* d_in, const int* in_sizes, int n_in,
                              void* d_out, int out_size)
{
    const float* values = (const float*)d_in[0];  // [D,S,B,H]
    const float* query  = (const float*)d_in[1];  // [H]
    const float* weight = (const float*)d_in[2];  // [H]
    float* out = (float*)d_out;                   // [S,B,H]

    const int H  = in_sizes[1];                   // 4096
    const int SB = out_size / H;                  // S*B = 4096

    fullattnres_kernel<<<SB * 2, NT>>>(values, query, weight, out, SB);
}

// round 9
// speedup vs baseline: 1.2265x; 1.2265x over previous
#include <cuda_runtime.h>

#define DDEPTH 8
#define HDIM   4096
#define NT     512
#define NWARP  (NT / 32)    // 16
#define HPT    8            // hidden dims per thread (512*8 = 4096)
#define EPSV   1e-6f

#define DOT4(a,b) ((a).x*(b).x + (a).y*(b).y + (a).z*(b).z + (a).w*(b).w)

// Persistent CTAs (2 per SM), one full site per loop iteration, online softmax
// over depth PAIRS (4 barriers/site). Last pair prefetches the next site's
// first pair -> continuous load stream across site boundaries.
__global__ __launch_bounds__(NT, 2)
void fullattnres_kernel(const float* __restrict__ values,
                        const float* __restrict__ query,
                        const float* __restrict__ weight,
                        float* __restrict__ out,
                        int SB)
{
    __shared__ float4 red[2][NWARP];   // {ss0,ss1,dp0,dp1} per warp, parity buf

    const int tid  = threadIdx.x;
    const int lane = tid & 31;
    const int warp = tid >> 5;
    const int h    = tid * HPT;
    const size_t dstr = (size_t)SB * HDIM;

    int site = blockIdx.x;
    if (site >= SB) return;

    // fused q*w, loaded ONCE per CTA (persistent)
    const float4 q0 = *(const float4*)(query + h);
    const float4 q1 = *(const float4*)(query + h + 4);
    const float4 w0 = *(const float4*)(weight + h);
    const float4 w1 = *(const float4*)(weight + h + 4);
    const float4 qw0 = make_float4(q0.x*w0.x, q0.y*w0.y, q0.z*w0.z, q0.w*w0.w);
    const float4 qw1 = make_float4(q1.x*w1.x, q1.y*w1.y, q1.z*w1.z, q1.w*w1.w);

    const float* p = values + (size_t)site * HDIM + h;

    // preload pair 0 (depths 0,1) of the first site
    float4 a0 = *(const float4*)(p);
    float4 a1 = *(const float4*)(p + 4);
    float4 b0 = *(const float4*)(p + dstr);
    float4 b1 = *(const float4*)(p + dstr + 4);

    int parity = 0;

    for (;;) {
        float  m = -3.402823466e38f;
        float  s = 0.f;
        float4 acc0 = make_float4(0.f, 0.f, 0.f, 0.f);
        float4 acc1 = make_float4(0.f, 0.f, 0.f, 0.f);

        #pragma unroll
        for (int pr = 0; pr < DDEPTH / 2; pr++) {
            // partials for depths 2pr (a) and 2pr+1 (b)
            float ss0 = DOT4(a0, a0) + DOT4(a1, a1);
            float dp0 = DOT4(qw0, a0) + DOT4(qw1, a1);
            float ss1 = DOT4(b0, b0) + DOT4(b1, b1);
            float dp1 = DOT4(qw0, b0) + DOT4(qw1, b1);

            // prefetch depth-A of the next pair (or next site's depth 0)
            float4 na0, na1, nb0, nb1;
            const float* pn;
            bool have_next = true;
            if (pr < DDEPTH / 2 - 1) {
                pn = p + (size_t)(2 * pr + 2) * dstr;
            } else {
                const int nsite = site + gridDim.x;
                have_next = (nsite < SB);
                pn = values + (size_t)(have_next ? nsite : site) * HDIM + h;
            }
            na0 = *(const float4*)(pn);
            na1 = *(const float4*)(pn + 4);

            // warp butterfly over the 4 scalars (in flight with the prefetch)
            #pragma unroll
            for (int off = 16; off > 0; off >>= 1) {
                ss0 += __shfl_xor_sync(0xFFFFFFFFu, ss0, off);
                ss1 += __shfl_xor_sync(0xFFFFFFFFu, ss1, off);
                dp0 += __shfl_xor_sync(0xFFFFFFFFu, dp0, off);
                dp1 += __shfl_xor_sync(0xFFFFFFFFu, dp1, off);
            }
            if (lane == 0)
                red[parity][warp] = make_float4(ss0, ss1, dp0, dp1);
            __syncthreads();

            // prefetch depth-B of the next pair (overlaps scan + softmax math)
            nb0 = *(const float4*)(pn + dstr);
            nb1 = *(const float4*)(pn + dstr + 4);

            // cross-warp scan: 16 broadcast LDS.128
            float4 t = make_float4(0.f, 0.f, 0.f, 0.f);
            #pragma unroll
            for (int w2 = 0; w2 < NWARP; w2++) {
                const float4 r = red[parity][w2];
                t.x += r.x;  t.y += r.y;  t.z += r.z;  t.w += r.w;
            }
            parity ^= 1;

            const float l0 = t.z * rsqrtf(t.x * (1.0f / HDIM) + EPSV);
            const float l1 = t.w * rsqrtf(t.y * (1.0f / HDIM) + EPSV);

            // joint online-softmax update for both depths
            const float mn = fmaxf(m, fmaxf(l0, l1));
            const float cs = __expf(m - mn);     // first pair: exp(-inf)=0
            const float e0 = __expf(l0 - mn);
            const float e1 = __expf(l1 - mn);
            s = s * cs + e0 + e1;
            acc0.x = acc0.x * cs + e0 * a0.x + e1 * b0.x;
            acc0.y = acc0.y * cs + e0 * a0.y + e1 * b0.y;
            acc0.z = acc0.z * cs + e0 * a0.z + e1 * b0.z;
            acc0.w = acc0.w * cs + e0 * a0.w + e1 * b0.w;
            acc1.x = acc1.x * cs + e0 * a1.x + e1 * b1.x;
            acc1.y = acc1.y * cs + e0 * a1.y + e1 * b1.y;
            acc1.z = acc1.z * cs + e0 * a1.z + e1 * b1.z;
            acc1.w = acc1.w * cs + e0 * a1.w + e1 * b1.w;
            m = mn;

            a0 = na0;  a1 = na1;  b0 = nb0;  b1 = nb1;
            (void)have_next;
        }

        // finalize + store this site
        const float inv = 1.0f / s;
        const size_t ob = (size_t)site * HDIM + h;
        *(float4*)(out + ob)     = make_float4(acc0.x*inv, acc0.y*inv, acc0.z*inv, acc0.w*inv);
        *(float4*)(out + ob + 4) = make_float4(acc1.x*inv, acc1.y*inv, acc1.z*inv, acc1.w*inv);

        site += gridDim.x;
        if (site >= SB) break;
        p = values + (size_t)site * HDIM + h;
        // a/b already hold the new site's pair 0 (prefetched at pr==3)
    }
}

extern "C" void kernel_launch(void* const* d_in, const int* in_sizes, int n_in,
                              void* d_out, int out_size)
{
    const float* values = (const float*)d_in[0];  // [D,S,B,H]
    const float* query  = (const float*)d_in[1];  // [H]
    const float* weight = (const float*)d_in[2];  // [H]
    float* out = (float*)d_out;                   // [S,B,H]

    const int H  = in_sizes[1];                   // 4096
    const int SB = out_size / H;                  // S*B = 4096

    int sms = 148;
    cudaDeviceGetAttribute(&sms, cudaDevAttrMultiProcessorCount, 0);
    int grid = 2 * sms;                           // persistent: 2 CTAs per SM
    if (grid > SB) grid = SB;

    fullattnres_kernel<<<grid, NT>>>(values, query, weight, out, SB);
}